// round 3
// baseline (speedup 1.0000x reference)
#include <cuda_runtime.h>

#define N_NODES 100000
#define E_MAX   3200000
#define F_IN    495
#define FH      16

// ---- scratch (no allocations allowed). float4 arrays -> guaranteed 16B alignment ----
static __device__ float  d_deg [N_NODES];
static __device__ float  d_dinv[N_NODES];
static __device__ float4 d_g   [N_NODES * 4];   // 16 floats per node
static __device__ float4 d_agg [N_NODES * 4];
static __device__ int    d_srci[E_MAX];
static __device__ int    d_dsti[E_MAX];
static __device__ float  d_p   [N_NODES];
static __device__ float  d_q   [N_NODES];
static __device__ int    d_is64;

// ---------------------------------------------------------------- dtype sniff:
// If edge_index is int64 (little-endian, values in [0,1e5)), every odd 32-bit
// word is a zero high-word. If int32, odd words are random node ids (~all nonzero).
// Samples stay within the first 8KB (safe under either dtype).
__global__ void k_detect(const int* __restrict__ w) {
    __shared__ int nz;
    if (threadIdx.x == 0) nz = 0;
    __syncthreads();
    int any = 0;
    for (int i = threadIdx.x; i < 1024; i += blockDim.x)
        if (w[2 * i + 1] != 0) any = 1;
    if (any) atomicOr(&nz, 1);
    __syncthreads();
    if (threadIdx.x == 0) d_is64 = (nz == 0) ? 1 : 0;
}

// ---------------------------------------------------------------- init deg=1 (self loop)
__global__ void k_init_deg(int n) {
    int v = blockIdx.x * blockDim.x + threadIdx.x;
    if (v < n) d_deg[v] = 1.0f;
}

// ---------------------------------------------------------------- index decode (either width) + degree count
__global__ void k_conv_deg(const void* __restrict__ ei, int e, int n) {
    int i = blockIdx.x * blockDim.x + threadIdx.x;
    if (i >= e) return;
    int s, d;
    if (d_is64) {
        const long long* p = (const long long*)ei;
        s = (int)p[i];
        d = (int)p[e + i];
    } else {
        const int* p = (const int*)ei;
        s = p[i];
        d = p[e + i];
    }
    if ((unsigned)s >= (unsigned)n) s = 0;   // defensive: never crash, fail loudly via rel_err
    if ((unsigned)d >= (unsigned)n) d = 0;
    d_srci[i] = s;
    d_dsti[i] = d;
    atomicAdd(&d_deg[d], 1.0f);
}

// ---------------------------------------------------------------- dinv = rsqrt(deg)
__global__ void k_dinv(int n) {
    int v = blockIdx.x * blockDim.x + threadIdx.x;
    if (v < n) d_dinv[v] = rsqrtf(d_deg[v]);
}

// ---------------------------------------------------------------- GEMM1: g = (x @ W1) * dinv ; agg = g
// 128 threads = 4 warps; warp handles 32 rows (lane = row). x staged in shared
// (row stride 132 floats -> conflict-free LDS.128). W zero-padded to K=512.
#define GM_ROWS   128
#define GM_TILEK  128
#define GM_KPAD   512
#define GM_XPITCH 132
#define GM_SMEM_FLOATS (GM_KPAD * FH + GM_ROWS * GM_XPITCH)

__global__ void __launch_bounds__(128) k_gemm1(const float* __restrict__ x,
                                               const float* __restrict__ W1, int n) {
    extern __shared__ float sm[];
    float* Ws = sm;                    // [512][16], zero padded
    float* xs = sm + GM_KPAD * FH;     // [128][132]

    int tid  = threadIdx.x;
    int lane = tid & 31;
    int warp = tid >> 5;
    int row0 = blockIdx.x * GM_ROWS;
    int row  = row0 + warp * 32 + lane;

    for (int i = tid; i < GM_KPAD * FH; i += 128)
        Ws[i] = (i < F_IN * FH) ? W1[i] : 0.0f;

    float acc[FH];
#pragma unroll
    for (int j = 0; j < FH; j++) acc[j] = 0.0f;

    for (int t = 0; t < 4; t++) {
        int k0 = t * GM_TILEK;
        __syncthreads();
        // stage x tile: thread tid loads column (k0+tid) for all 128 rows (coalesced)
        for (int r = 0; r < GM_ROWS; r++) {
            int gr = row0 + r;
            int gk = k0 + tid;
            xs[r * GM_XPITCH + tid] = (gr < n && gk < F_IN) ? x[(long long)gr * F_IN + gk] : 0.0f;
        }
        __syncthreads();

        const float4* xr = (const float4*)&xs[(warp * 32 + lane) * GM_XPITCH];
#pragma unroll 4
        for (int kq = 0; kq < GM_TILEK / 4; kq++) {
            float4 xv = xr[kq];
            const float4* w4 = (const float4*)&Ws[(k0 + 4 * kq) * FH];
#pragma unroll
            for (int i = 0; i < 4; i++) {
                float xi = (i == 0) ? xv.x : (i == 1) ? xv.y : (i == 2) ? xv.z : xv.w;
                float4 b0 = w4[i * 4 + 0];
                float4 b1 = w4[i * 4 + 1];
                float4 b2 = w4[i * 4 + 2];
                float4 b3 = w4[i * 4 + 3];
                acc[0]  = fmaf(xi, b0.x, acc[0]);
                acc[1]  = fmaf(xi, b0.y, acc[1]);
                acc[2]  = fmaf(xi, b0.z, acc[2]);
                acc[3]  = fmaf(xi, b0.w, acc[3]);
                acc[4]  = fmaf(xi, b1.x, acc[4]);
                acc[5]  = fmaf(xi, b1.y, acc[5]);
                acc[6]  = fmaf(xi, b1.z, acc[6]);
                acc[7]  = fmaf(xi, b1.w, acc[7]);
                acc[8]  = fmaf(xi, b2.x, acc[8]);
                acc[9]  = fmaf(xi, b2.y, acc[9]);
                acc[10] = fmaf(xi, b2.z, acc[10]);
                acc[11] = fmaf(xi, b2.w, acc[11]);
                acc[12] = fmaf(xi, b3.x, acc[12]);
                acc[13] = fmaf(xi, b3.y, acc[13]);
                acc[14] = fmaf(xi, b3.z, acc[14]);
                acc[15] = fmaf(xi, b3.w, acc[15]);
            }
        }
    }

    if (row < n) {
        float di = d_dinv[row];
        float4* gp = &d_g[row * 4];
        float4* ap = &d_agg[row * 4];
#pragma unroll
        for (int qd = 0; qd < 4; qd++) {
            float4 v = make_float4(acc[4 * qd] * di, acc[4 * qd + 1] * di,
                                   acc[4 * qd + 2] * di, acc[4 * qd + 3] * di);
            gp[qd] = v;
            ap[qd] = v;
        }
    }
}

// ---------------------------------------------------------------- edge scatter: agg[dst] += g[src]
__global__ void k_scatter(int e) {
    int i = blockIdx.x * blockDim.x + threadIdx.x;
    if (i >= e) return;
    int s = d_srci[i];
    int d = d_dsti[i];
    const float4* gs = &d_g[s * 4];
    float4* ad = &d_agg[d * 4];
    float4 v0 = gs[0], v1 = gs[1], v2 = gs[2], v3 = gs[3];
    atomicAdd(ad + 0, v0);
    atomicAdd(ad + 1, v1);
    atomicAdd(ad + 2, v2);
    atomicAdd(ad + 3, v3);
}

// ---------------------------------------------------------------- layer1 finalize + layer2 GEMM:
// z1 = relu(dinv*agg + b1); g2 = (z1 @ W2) * dinv; g = agg = g2
__global__ void __launch_bounds__(256) k_mid(const float* __restrict__ W2,
                                             const float* __restrict__ b1, int n) {
    __shared__ float w2s[FH * FH];
    __shared__ float b1s[FH];
    int tid = threadIdx.x;
    if (tid < FH * FH) w2s[tid] = W2[tid];
    if (tid < FH) b1s[tid] = b1[tid];
    __syncthreads();

    int v = blockIdx.x * blockDim.x + tid;
    if (v >= n) return;
    float di = d_dinv[v];
    const float4* ap = &d_agg[v * 4];
    float z[FH];
#pragma unroll
    for (int qd = 0; qd < 4; qd++) {
        float4 a = ap[qd];
        z[4 * qd + 0] = fmaxf(fmaf(di, a.x, b1s[4 * qd + 0]), 0.0f);
        z[4 * qd + 1] = fmaxf(fmaf(di, a.y, b1s[4 * qd + 1]), 0.0f);
        z[4 * qd + 2] = fmaxf(fmaf(di, a.z, b1s[4 * qd + 2]), 0.0f);
        z[4 * qd + 3] = fmaxf(fmaf(di, a.w, b1s[4 * qd + 3]), 0.0f);
    }
    float h[FH];
#pragma unroll
    for (int j = 0; j < FH; j++) h[j] = 0.0f;
#pragma unroll
    for (int k = 0; k < FH; k++) {
        float zk = z[k];
#pragma unroll
        for (int j = 0; j < FH; j++) h[j] = fmaf(zk, w2s[k * FH + j], h[j]);
    }
    float4* gp = &d_g[v * 4];
    float4* ap2 = &d_agg[v * 4];
#pragma unroll
    for (int qd = 0; qd < 4; qd++) {
        float4 o = make_float4(h[4 * qd] * di, h[4 * qd + 1] * di,
                               h[4 * qd + 2] * di, h[4 * qd + 3] * di);
        gp[qd] = o;
        ap2[qd] = o;
    }
}

// ---------------------------------------------------------------- layer2 finalize + separable FC:
// z2 = relu(dinv*agg + b2); p = z2 . Wfc[:16]; q = z2 . Wfc[16:]
__global__ void __launch_bounds__(256) k_fin2(const float* __restrict__ b2,
                                              const float* __restrict__ Wfc, int n) {
    __shared__ float wfs[2 * FH];
    __shared__ float b2s[FH];
    int tid = threadIdx.x;
    if (tid < 2 * FH) wfs[tid] = Wfc[tid];
    if (tid < FH) b2s[tid] = b2[tid];
    __syncthreads();

    int v = blockIdx.x * blockDim.x + tid;
    if (v >= n) return;
    float di = d_dinv[v];
    const float4* ap = &d_agg[v * 4];
    float p = 0.0f, q = 0.0f;
#pragma unroll
    for (int qd = 0; qd < 4; qd++) {
        float4 a = ap[qd];
        float zz[4];
        zz[0] = fmaxf(fmaf(di, a.x, b2s[4 * qd + 0]), 0.0f);
        zz[1] = fmaxf(fmaf(di, a.y, b2s[4 * qd + 1]), 0.0f);
        zz[2] = fmaxf(fmaf(di, a.z, b2s[4 * qd + 2]), 0.0f);
        zz[3] = fmaxf(fmaf(di, a.w, b2s[4 * qd + 3]), 0.0f);
#pragma unroll
        for (int u = 0; u < 4; u++) {
            p = fmaf(zz[u], wfs[4 * qd + u], p);
            q = fmaf(zz[u], wfs[FH + 4 * qd + u], q);
        }
    }
    d_p[v] = p;
    d_q[v] = q;
}

// ---------------------------------------------------------------- out[e] = p[src] + q[dst] + bfc
__global__ void k_edge(const float* __restrict__ bfc, float* __restrict__ out, int e) {
    int i = blockIdx.x * blockDim.x + threadIdx.x;
    if (i >= e) return;
    out[i] = d_p[d_srci[i]] + d_q[d_dsti[i]] + bfc[0];
}

// ----------------------------------------------------------------
extern "C" void kernel_launch(void* const* d_in, const int* in_sizes, int n_in,
                              void* d_out, int out_size) {
    const float* x    = (const float*)d_in[0];
    const void*  ei   = d_in[1];
    const float* W1   = (const float*)d_in[2];
    const float* b1   = (const float*)d_in[3];
    const float* W2   = (const float*)d_in[4];
    const float* b2   = (const float*)d_in[5];
    const float* Wfc  = (const float*)d_in[6];
    const float* bfc  = (const float*)d_in[7];
    float*       out  = (float*)d_out;

    int n = in_sizes[0] / F_IN;      // 100000
    int e = in_sizes[1] / 2;         // 3200000

    static const int smem_bytes = GM_SMEM_FLOATS * (int)sizeof(float);
    cudaFuncSetAttribute(k_gemm1, cudaFuncAttributeMaxDynamicSharedMemorySize, smem_bytes);

    int nb_n  = (n + 255) / 256;
    int nb_e  = (e + 255) / 256;
    int nb_gm = (n + GM_ROWS - 1) / GM_ROWS;

    k_detect<<<1, 256>>>((const int*)ei);
    k_init_deg<<<nb_n, 256>>>(n);
    k_conv_deg<<<nb_e, 256>>>(ei, e, n);
    k_dinv<<<nb_n, 256>>>(n);
    k_gemm1<<<nb_gm, 128, smem_bytes>>>(x, W1, n);
    k_scatter<<<nb_e, 256>>>(e);
    k_mid<<<nb_n, 256>>>(W2, b1, n);
    k_scatter<<<nb_e, 256>>>(e);
    k_fin2<<<nb_n, 256>>>(b2, Wfc, n);
    k_edge<<<nb_e, 256>>>(bfc, out, e);
}